// round 13
// baseline (speedup 1.0000x reference)
#include <cuda_runtime.h>
#include <cuda_fp16.h>
#include <cstdint>

#define NNODES 100000
#define FEAT   128
#define NEDGES 1600000
#define ETOT   (NEDGES + NNODES)
#define BN_EPS 1e-5f
#define NEG_SLOPE 0.2f
#define LDX    136   // padded smem row pitch in halves (272B: conflict-free ldmatrix)
#define SCAN_BLOCKS ((NNODES + 1023) / 1024)   // 98
#define EWARPS 32   // warps (dsts) per edge block

// ---------------- static device scratch ----------------
__device__ __half g_hh[(size_t)NNODES * FEAT];    // h of current layer (fp16)
__device__ __half g_acch[(size_t)NNODES * FEAT];  // inter-layer activation (fp16)
__device__ __half g_Wh[3][FEAT * FEAT];           // fp16 weights
__device__ float  g_as[NNODES];
__device__ float  g_ad[NNODES];
__device__ int    g_cnt[NNODES];
__device__ int    g_rowptr[NNODES + 1];
__device__ int    g_off[NNODES];
__device__ int    g_csrc[ETOT];
__device__ int    g_bsum[SCAN_BLOCKS];
__device__ float  g_bnsum0[FEAT], g_bnsq0[FEAT];
__device__ float  g_bnsum1[FEAT], g_bnsq1[FEAT];

// ---------------- weight convert + zero cnt/BN ----------------
__global__ void convw_kernel(const float* __restrict__ W0,
                             const float* __restrict__ W1,
                             const float* __restrict__ W2) {
    int i = blockIdx.x * blockDim.x + threadIdx.x;
    if (i < NNODES) g_cnt[i] = 0;
    if (i < FEAT) {
        g_bnsum0[i] = 0.f; g_bnsq0[i] = 0.f;
        g_bnsum1[i] = 0.f; g_bnsq1[i] = 0.f;
    }
    if (i < FEAT * FEAT) {
        g_Wh[0][i] = __float2half(W0[i]);
        g_Wh[1][i] = __float2half(W1[i]);
        g_Wh[2][i] = __float2half(W2[i]);
    }
}

// 4 edges per thread (NEDGES % 4 == 0)
__global__ void count_kernel(const int* __restrict__ ei) {
    int e = blockIdx.x * blockDim.x + threadIdx.x;
    if (e < NEDGES / 4) {
        int4 d = ((const int4*)(ei + NEDGES))[e];
        atomicAdd(&g_cnt[d.x], 1);
        atomicAdd(&g_cnt[d.y], 1);
        atomicAdd(&g_cnt[d.z], 1);
        atomicAdd(&g_cnt[d.w], 1);
    }
}

// ---------------- scan phase 1: per-block inclusive scan of (cnt+1) ----------------
__global__ __launch_bounds__(1024) void scan1_kernel() {
    __shared__ int wsum[32];
    int tid = threadIdx.x, lane = tid & 31, wid = tid >> 5;
    int i = blockIdx.x * 1024 + tid;
    int v = (i < NNODES) ? g_cnt[i] + 1 : 0;   // +1 = self loop
    int s = v;
#pragma unroll
    for (int o = 1; o < 32; o <<= 1) {
        int t = __shfl_up_sync(0xffffffffu, s, o);
        if (lane >= o) s += t;
    }
    if (lane == 31) wsum[wid] = s;
    __syncthreads();
    if (wid == 0) {
        int ws = wsum[lane];
#pragma unroll
        for (int o = 1; o < 32; o <<= 1) {
            int t = __shfl_up_sync(0xffffffffu, ws, o);
            if (lane >= o) ws += t;
        }
        wsum[lane] = ws;
    }
    __syncthreads();
    int incl = s + (wid ? wsum[wid - 1] : 0);
    if (i < NNODES) g_rowptr[i + 1] = incl;
    if (tid == 1023) g_bsum[blockIdx.x] = incl;
}

// ---------------- scan phase 2+3 fused ----------------
__global__ __launch_bounds__(1024) void scan23_kernel() {
    __shared__ int wred[32];
    int tid = threadIdx.x, lane = tid & 31, wid = tid >> 5;
    int v = (tid < SCAN_BLOCKS && tid < blockIdx.x) ? g_bsum[tid] : 0;
#pragma unroll
    for (int o = 16; o; o >>= 1) v += __shfl_xor_sync(0xffffffffu, v, o);
    if (lane == 0) wred[wid] = v;
    __syncthreads();
    if (wid == 0) {
        int t = wred[lane];
#pragma unroll
        for (int o = 16; o; o >>= 1) t += __shfl_xor_sync(0xffffffffu, t, o);
        if (lane == 0) wred[0] = t;
    }
    __syncthreads();
    int carry = wred[0];
    int i = blockIdx.x * 1024 + tid;
    if (i == 0) g_rowptr[0] = 0;
    if (i < NNODES) {
        int incl = g_rowptr[i + 1] + carry;
        g_rowptr[i + 1] = incl;
        g_off[i] = incl - (g_cnt[i] + 1);
    }
}

// 4 edges per thread + self-loop tail range (NNODES % 4 == 0)
__global__ void scatter_kernel(const int* __restrict__ ei) {
    int idx = blockIdx.x * blockDim.x + threadIdx.x;
    const int EQ = NEDGES / 4;
    if (idx < EQ) {
        int4 s4 = ((const int4*)ei)[idx];
        int4 d4 = ((const int4*)(ei + NEDGES))[idx];
        int p;
        p = atomicAdd(&g_off[d4.x], 1); g_csrc[p] = s4.x;
        p = atomicAdd(&g_off[d4.y], 1); g_csrc[p] = s4.y;
        p = atomicAdd(&g_off[d4.z], 1); g_csrc[p] = s4.z;
        p = atomicAdd(&g_off[d4.w], 1); g_csrc[p] = s4.w;
    } else if (idx < EQ + NNODES / 4) {
        int n0 = (idx - EQ) * 4;
#pragma unroll
        for (int j = 0; j < 4; j++) {
            int n = n0 + j;
            int p = atomicAdd(&g_off[n], 1);
            g_csrc[p] = n;
        }
    }
}

// ---------------- tensor-core helpers ----------------
__device__ __forceinline__ uint32_t smem_u32(const void* p) {
    uint32_t a;
    asm("{ .reg .u64 t; cvta.to.shared.u64 t, %1; cvt.u32.u64 %0, t; }"
        : "=r"(a) : "l"(p));
    return a;
}

__device__ __forceinline__ void ldsm_x4(uint32_t& a0, uint32_t& a1, uint32_t& a2,
                                        uint32_t& a3, uint32_t addr) {
    asm volatile("ldmatrix.sync.aligned.m8n8.x4.shared.b16 {%0,%1,%2,%3}, [%4];"
                 : "=r"(a0), "=r"(a1), "=r"(a2), "=r"(a3) : "r"(addr));
}

__device__ __forceinline__ void ldsm_x2(uint32_t& b0, uint32_t& b1, uint32_t addr) {
    asm volatile("ldmatrix.sync.aligned.m8n8.x2.shared.b16 {%0,%1}, [%2];"
                 : "=r"(b0), "=r"(b1) : "r"(addr));
}

__device__ __forceinline__ void mma16816(float c[4], uint32_t a0, uint32_t a1,
                                         uint32_t a2, uint32_t a3,
                                         uint32_t b0, uint32_t b1) {
    asm volatile(
        "mma.sync.aligned.m16n8k16.row.col.f32.f16.f16.f32 "
        "{%0,%1,%2,%3}, {%4,%5,%6,%7}, {%8,%9}, {%0,%1,%2,%3};"
        : "+f"(c[0]), "+f"(c[1]), "+f"(c[2]), "+f"(c[3])
        : "r"(a0), "r"(a1), "r"(a2), "r"(a3), "r"(b0), "r"(b1));
}

// ---------------- GEMM (HMMA) + fused BN-on-load + alpha epilogue ----------------
__global__ __launch_bounds__(256) void gemm_kernel(
    const float* __restrict__ Xf, const __half* __restrict__ Xh,
    const __half* __restrict__ Wh,
    const float* __restrict__ asrc, const float* __restrict__ adst,
    const float* __restrict__ gamma, const float* __restrict__ beta,
    const float* __restrict__ bsum, const float* __restrict__ bsq,
    int use_bn, int M) {
    extern __shared__ __half smem[];
    __half* Xs = smem;                       // [128][LDX]
    __half* Ws = smem + 128 * LDX;           // [128][LDX]
    float* sc  = (float*)(smem + 2 * 128 * LDX);
    float* sh  = sc + FEAT;
    float* sAs = sh + FEAT;
    float* sAd = sAs + FEAT;

    int tid = threadIdx.x;
    int bm = blockIdx.x * 128;

    if (tid < FEAT) {
        sAs[tid] = asrc[tid];
        sAd[tid] = adst[tid];
        if (use_bn) {
            const float invN = 1.f / (float)NNODES;
            float mu = bsum[tid] * invN;
            float var = bsq[tid] * invN - mu * mu;
            float s = gamma[tid] * rsqrtf(var + BN_EPS);
            sc[tid] = s;
            sh[tid] = beta[tid] - mu * s;
        } else { sc[tid] = 1.f; sh[tid] = 0.f; }
    }
    __syncthreads();

    for (int idx = tid; idx < 2048; idx += 256) {
        int r = idx >> 4, c = (idx & 15) << 3;
        *(uint4*)&Ws[r * LDX + c] = *(const uint4*)&Wh[r * FEAT + c];
    }
    if (Xh) {
        for (int idx = tid; idx < 2048; idx += 256) {
            int r = idx >> 4, c = (idx & 15) << 3;
            int gr = bm + r;
            uint4 u = make_uint4(0u, 0u, 0u, 0u);
            if (gr < M) u = *(const uint4*)&Xh[(size_t)gr * FEAT + c];
            __half2* hp = (__half2*)&u;
            uint4 outv;
            __half2* op = (__half2*)&outv;
#pragma unroll
            for (int j = 0; j < 4; j++) {
                float2 f = __half22float2(hp[j]);
                int cc = c + j * 2;
                float y0 = f.x * sc[cc] + sh[cc];
                float y1 = f.y * sc[cc + 1] + sh[cc + 1];
                y0 = fmaxf(y0, 0.f); y1 = fmaxf(y1, 0.f);
                op[j] = __floats2half2_rn(y0, y1);
            }
            *(uint4*)&Xs[r * LDX + c] = outv;
        }
    } else {
        for (int idx = tid; idx < 4096; idx += 256) {
            int r = idx >> 5, c = (idx & 31) << 2;
            int gr = bm + r;
            float4 xv = make_float4(0.f, 0.f, 0.f, 0.f);
            if (gr < M) xv = *(const float4*)&Xf[(size_t)gr * FEAT + c];
            __half2 h0 = __floats2half2_rn(xv.x, xv.y);
            __half2 h1 = __floats2half2_rn(xv.z, xv.w);
            uint2 u; u.x = *(uint32_t*)&h0; u.y = *(uint32_t*)&h1;
            *(uint2*)&Xs[r * LDX + c] = u;
        }
    }
    __syncthreads();

    int warp = tid >> 5, lane = tid & 31;
    int m0 = warp * 16;

    float c_[16][4];
#pragma unroll
    for (int t = 0; t < 16; t++)
#pragma unroll
        for (int j = 0; j < 4; j++) c_[t][j] = 0.f;

    uint32_t sbase = smem_u32(smem);
    uint32_t xs_addr = sbase + ((m0 + (lane & 15)) * LDX + (lane >> 4) * 8) * 2;
    uint32_t ws_addr = sbase + (128 * LDX + (lane & 7) * LDX + ((lane >> 3) & 1) * 8) * 2;

#pragma unroll
    for (int k = 0; k < 8; k++) {
        uint32_t a0, a1, a2, a3;
        ldsm_x4(a0, a1, a2, a3, xs_addr + k * 32);
#pragma unroll
        for (int t = 0; t < 16; t++) {
            uint32_t b0, b1;
            ldsm_x2(b0, b1, ws_addr + (t * 8 * LDX) * 2 + k * 32);
            mma16816(c_[t], a0, a1, a2, a3, b0, b1);
        }
    }

    // ---- alpha epilogue
    int r0l = lane >> 2;
    int q = (lane & 3) * 2;
    float ps0 = 0.f, pd0 = 0.f, ps1 = 0.f, pd1 = 0.f;
#pragma unroll
    for (int t = 0; t < 16; t++) {
        int cA = t * 8 + q;
        float a0 = sAs[cA], a1 = sAs[cA + 1];
        float d0 = sAd[cA], d1 = sAd[cA + 1];
        ps0 += c_[t][0] * a0 + c_[t][1] * a1;
        pd0 += c_[t][0] * d0 + c_[t][1] * d1;
        ps1 += c_[t][2] * a0 + c_[t][3] * a1;
        pd1 += c_[t][2] * d0 + c_[t][3] * d1;
    }
#pragma unroll
    for (int o = 1; o < 4; o <<= 1) {
        ps0 += __shfl_xor_sync(0xffffffffu, ps0, o);
        pd0 += __shfl_xor_sync(0xffffffffu, pd0, o);
        ps1 += __shfl_xor_sync(0xffffffffu, ps1, o);
        pd1 += __shfl_xor_sync(0xffffffffu, pd1, o);
    }
    int gr0 = bm + m0 + r0l, gr1 = gr0 + 8;
    if ((lane & 3) == 0) {
        if (gr0 < M) { g_as[gr0] = ps0; g_ad[gr0] = pd0; }
        if (gr1 < M) { g_as[gr1] = ps1; g_ad[gr1] = pd1; }
    }

    // ---- stage C (fp16) into this warp's own Xs rows, then coalesced store
#pragma unroll
    for (int t = 0; t < 16; t++) {
        int colp = t * 8 + q;
        __half2 lo = __floats2half2_rn(c_[t][0], c_[t][1]);
        __half2 hi = __floats2half2_rn(c_[t][2], c_[t][3]);
        *(__half2*)&Xs[(m0 + r0l) * LDX + colp] = lo;
        *(__half2*)&Xs[(m0 + r0l + 8) * LDX + colp] = hi;
    }
    __syncwarp();
    for (int i = lane; i < 256; i += 32) {
        int r = i >> 4, ch = (i & 15) << 3;
        int gr = bm + m0 + r;
        if (gr < M)
            *(uint4*)&g_hh[(size_t)gr * FEAT + ch] = *(uint4*)&Xs[(m0 + r) * LDX + ch];
    }
}

__device__ __forceinline__ float leaky(float x) {
    return x >= 0.f ? x : NEG_SLOPE * x;
}

// ---------------- single-pass edge aggregation: half-warp per edge ----------------
__global__ __launch_bounds__(32 * EWARPS) void edge_kernel(const float* __restrict__ bias,
                                                           float* __restrict__ outf,
                                                           __half* __restrict__ outh,
                                                           float* __restrict__ bnsum,
                                                           float* __restrict__ bnsq,
                                                           int do_bn) {
    __shared__ float psum[EWARPS][128];
    __shared__ float psq[EWARPS][128];
    int tid = threadIdx.x, w = tid >> 5, lane = tid & 31;
    int half = lane >> 4, hl = lane & 15;
    int d = blockIdx.x * EWARPS + w;       // grid = NNODES/EWARPS exactly
    int beg = g_rowptr[d], end = g_rowptr[d + 1];
    float ad = g_ad[d];

    float acc[8];
#pragma unroll
    for (int j = 0; j < 8; j++) acc[j] = 0.f;
    float wsum = 0.f;

    const uint4* h4 = (const uint4*)g_hh;   // 16 uint4 per node row
    int i = beg;
#pragma unroll 4
    for (; i + 2 <= end; i += 2) {
        int s = g_csrc[i + half];
        float wt = __expf(leaky(g_as[s] + ad));
        wsum += wt;
        uint4 raw = h4[(size_t)s * 16 + hl];
        __half2* hp = (__half2*)&raw;
#pragma unroll
        for (int j = 0; j < 4; j++) {
            float2 f = __half22float2(hp[j]);
            acc[2 * j]     += wt * f.x;
            acc[2 * j + 1] += wt * f.y;
        }
    }
    if (i < end && half == 0) {            // odd tail edge
        int s = g_csrc[i];
        float wt = __expf(leaky(g_as[s] + ad));
        wsum += wt;
        uint4 raw = h4[(size_t)s * 16 + hl];
        __half2* hp = (__half2*)&raw;
#pragma unroll
        for (int j = 0; j < 4; j++) {
            float2 f = __half22float2(hp[j]);
            acc[2 * j]     += wt * f.x;
            acc[2 * j + 1] += wt * f.y;
        }
    }
#pragma unroll
    for (int j = 0; j < 8; j++)
        acc[j] += __shfl_down_sync(0xffffffffu, acc[j], 16);
    wsum += __shfl_down_sync(0xffffffffu, wsum, 16);

    if (half == 0) {
        float inv = 1.f / wsum;
        float4 b0 = ((const float4*)bias)[hl * 2];
        float4 b1 = ((const float4*)bias)[hl * 2 + 1];
        float o[8];
        o[0] = acc[0] * inv + b0.x; o[1] = acc[1] * inv + b0.y;
        o[2] = acc[2] * inv + b0.z; o[3] = acc[3] * inv + b0.w;
        o[4] = acc[4] * inv + b1.x; o[5] = acc[5] * inv + b1.y;
        o[6] = acc[6] * inv + b1.z; o[7] = acc[7] * inv + b1.w;
        if (outf) {
            ((float4*)outf)[(size_t)d * 32 + hl * 2]     = make_float4(o[0], o[1], o[2], o[3]);
            ((float4*)outf)[(size_t)d * 32 + hl * 2 + 1] = make_float4(o[4], o[5], o[6], o[7]);
        } else {
            __half2 q0 = __floats2half2_rn(o[0], o[1]);
            __half2 q1 = __floats2half2_rn(o[2], o[3]);
            __half2 q2 = __floats2half2_rn(o[4], o[5]);
            __half2 q3 = __floats2half2_rn(o[6], o[7]);
            uint4 u;
            u.x = *(uint32_t*)&q0; u.y = *(uint32_t*)&q1;
            u.z = *(uint32_t*)&q2; u.w = *(uint32_t*)&q3;
            ((uint4*)outh)[(size_t)d * 16 + hl] = u;
        }
        if (do_bn) {
            *(float4*)&psum[w][hl * 8]     = make_float4(o[0], o[1], o[2], o[3]);
            *(float4*)&psum[w][hl * 8 + 4] = make_float4(o[4], o[5], o[6], o[7]);
            *(float4*)&psq[w][hl * 8]      = make_float4(o[0]*o[0], o[1]*o[1], o[2]*o[2], o[3]*o[3]);
            *(float4*)&psq[w][hl * 8 + 4]  = make_float4(o[4]*o[4], o[5]*o[5], o[6]*o[6], o[7]*o[7]);
        }
    }

    if (do_bn) {
        __syncthreads();
        if (tid < FEAT) {
            float s = 0.f, q = 0.f;
#pragma unroll
            for (int ww = 0; ww < EWARPS; ww++) {
                s += psum[ww][tid];
                q += psq[ww][tid];
            }
            atomicAdd(&bnsum[tid], s);
            atomicAdd(&bnsq[tid], q);
        }
    }
}

// ---------------- launch ----------------
extern "C" void kernel_launch(void* const* d_in, const int* in_sizes, int n_in,
                              void* d_out, int out_size) {
    const float* x  = (const float*)d_in[0];
    const int*   ei = (const int*)d_in[1];
    const float* W[3]  = {(const float*)d_in[2], (const float*)d_in[6],  (const float*)d_in[10]};
    const float* As[3] = {(const float*)d_in[3], (const float*)d_in[7],  (const float*)d_in[11]};
    const float* Ad[3] = {(const float*)d_in[4], (const float*)d_in[8],  (const float*)d_in[12]};
    const float* B[3]  = {(const float*)d_in[5], (const float*)d_in[9],  (const float*)d_in[13]};
    const float* gam[2] = {(const float*)d_in[14], (const float*)d_in[16]};
    const float* bet[2] = {(const float*)d_in[15], (const float*)d_in[17]};

    float *bs0, *bq0, *bs1, *bq1;
    __half *wh_ptr, *acch_ptr;
    cudaGetSymbolAddress((void**)&bs0, g_bnsum0);
    cudaGetSymbolAddress((void**)&bq0, g_bnsq0);
    cudaGetSymbolAddress((void**)&bs1, g_bnsum1);
    cudaGetSymbolAddress((void**)&bq1, g_bnsq1);
    cudaGetSymbolAddress((void**)&wh_ptr, g_Wh);
    cudaGetSymbolAddress((void**)&acch_ptr, g_acch);

    const int SMEM_GEMM = (2 * 128 * LDX) * 2 + 4 * FEAT * 4;   // 71680 B
    cudaFuncSetAttribute(gemm_kernel,
                         cudaFuncAttributeMaxDynamicSharedMemorySize, SMEM_GEMM);

    // CSR build (dense, R8 pipeline)
    convw_kernel<<<(NNODES + 255) / 256, 256>>>(W[0], W[1], W[2]);
    count_kernel<<<(NEDGES / 4 + 255) / 256, 256>>>(ei);
    scan1_kernel<<<SCAN_BLOCKS, 1024>>>();
    scan23_kernel<<<SCAN_BLOCKS, 1024>>>();
    scatter_kernel<<<((NEDGES + NNODES) / 4 + 255) / 256, 256>>>(ei);

    const int gemm_grid = (NNODES + 127) / 128;       // 782
    const int edge_grid = NNODES / EWARPS;            // 3125, exact

    // layer 0 (fp32 X input, no BN)
    gemm_kernel<<<gemm_grid, 256, SMEM_GEMM>>>(x, nullptr, wh_ptr, As[0], Ad[0],
                                               nullptr, nullptr, nullptr, nullptr, 0, NNODES);
    edge_kernel<<<edge_grid, 32 * EWARPS>>>(B[0], nullptr, acch_ptr, bs0, bq0, 1);
    // layer 1 (fp16 X, BN0+relu fused)
    gemm_kernel<<<gemm_grid, 256, SMEM_GEMM>>>(nullptr, acch_ptr, wh_ptr + FEAT * FEAT,
                                               As[1], Ad[1], gam[0], bet[0], bs0, bq0, 1, NNODES);
    edge_kernel<<<edge_grid, 32 * EWARPS>>>(B[1], nullptr, acch_ptr, bs1, bq1, 1);
    // layer 2 (fp16 X, BN1+relu fused, fp32 output)
    gemm_kernel<<<gemm_grid, 256, SMEM_GEMM>>>(nullptr, acch_ptr, wh_ptr + 2 * FEAT * FEAT,
                                               As[2], Ad[2], gam[1], bet[1], bs1, bq1, 1, NNODES);
    edge_kernel<<<edge_grid, 32 * EWARPS>>>(B[2], (float*)d_out, nullptr, nullptr, nullptr, 0);
}

// round 14
// speedup vs baseline: 1.0264x; 1.0264x over previous
#include <cuda_runtime.h>
#include <cuda_fp16.h>
#include <cstdint>

#define NNODES 100000
#define FEAT   128
#define NEDGES 1600000
#define ETOT   (NEDGES + NNODES)
#define BN_EPS 1e-5f
#define NEG_SLOPE 0.2f
#define LDX    136   // padded smem row pitch in halves (272B: conflict-free ldmatrix)
#define SCAN_BLOCKS ((NNODES + 1023) / 1024)   // 98
#define EWARPS 16   // warps (dsts) per edge block — measured optimum (8:319.7, 16:313.9, 32:321.7)

// ---------------- static device scratch ----------------
__device__ __half g_hh[(size_t)NNODES * FEAT];    // h of current layer (fp16)
__device__ __half g_acch[(size_t)NNODES * FEAT];  // inter-layer activation (fp16)
__device__ __half g_Wh[3][FEAT * FEAT];           // fp16 weights
__device__ float  g_as[NNODES];
__device__ float  g_ad[NNODES];
__device__ int    g_cnt[NNODES];
__device__ int    g_rowptr[NNODES + 1];
__device__ int    g_off[NNODES];
__device__ int    g_csrc[ETOT];
__device__ int    g_bsum[SCAN_BLOCKS];
__device__ float  g_bnsum0[FEAT], g_bnsq0[FEAT];
__device__ float  g_bnsum1[FEAT], g_bnsq1[FEAT];

// ---------------- weight convert + zero cnt/BN ----------------
__global__ void convw_kernel(const float* __restrict__ W0,
                             const float* __restrict__ W1,
                             const float* __restrict__ W2) {
    int i = blockIdx.x * blockDim.x + threadIdx.x;
    if (i < NNODES) g_cnt[i] = 0;
    if (i < FEAT) {
        g_bnsum0[i] = 0.f; g_bnsq0[i] = 0.f;
        g_bnsum1[i] = 0.f; g_bnsq1[i] = 0.f;
    }
    if (i < FEAT * FEAT) {
        g_Wh[0][i] = __float2half(W0[i]);
        g_Wh[1][i] = __float2half(W1[i]);
        g_Wh[2][i] = __float2half(W2[i]);
    }
}

// 4 edges per thread (NEDGES % 4 == 0)
__global__ void count_kernel(const int* __restrict__ ei) {
    int e = blockIdx.x * blockDim.x + threadIdx.x;
    if (e < NEDGES / 4) {
        int4 d = ((const int4*)(ei + NEDGES))[e];
        atomicAdd(&g_cnt[d.x], 1);
        atomicAdd(&g_cnt[d.y], 1);
        atomicAdd(&g_cnt[d.z], 1);
        atomicAdd(&g_cnt[d.w], 1);
    }
}

// ---------------- scan phase 1: per-block inclusive scan of (cnt+1) ----------------
__global__ __launch_bounds__(1024) void scan1_kernel() {
    __shared__ int wsum[32];
    int tid = threadIdx.x, lane = tid & 31, wid = tid >> 5;
    int i = blockIdx.x * 1024 + tid;
    int v = (i < NNODES) ? g_cnt[i] + 1 : 0;   // +1 = self loop
    int s = v;
#pragma unroll
    for (int o = 1; o < 32; o <<= 1) {
        int t = __shfl_up_sync(0xffffffffu, s, o);
        if (lane >= o) s += t;
    }
    if (lane == 31) wsum[wid] = s;
    __syncthreads();
    if (wid == 0) {
        int ws = wsum[lane];
#pragma unroll
        for (int o = 1; o < 32; o <<= 1) {
            int t = __shfl_up_sync(0xffffffffu, ws, o);
            if (lane >= o) ws += t;
        }
        wsum[lane] = ws;
    }
    __syncthreads();
    int incl = s + (wid ? wsum[wid - 1] : 0);
    if (i < NNODES) g_rowptr[i + 1] = incl;
    if (tid == 1023) g_bsum[blockIdx.x] = incl;
}

// ---------------- scan phase 2+3 fused ----------------
__global__ __launch_bounds__(1024) void scan23_kernel() {
    __shared__ int wred[32];
    int tid = threadIdx.x, lane = tid & 31, wid = tid >> 5;
    int v = (tid < SCAN_BLOCKS && tid < blockIdx.x) ? g_bsum[tid] : 0;
#pragma unroll
    for (int o = 16; o; o >>= 1) v += __shfl_xor_sync(0xffffffffu, v, o);
    if (lane == 0) wred[wid] = v;
    __syncthreads();
    if (wid == 0) {
        int t = wred[lane];
#pragma unroll
        for (int o = 16; o; o >>= 1) t += __shfl_xor_sync(0xffffffffu, t, o);
        if (lane == 0) wred[0] = t;
    }
    __syncthreads();
    int carry = wred[0];
    int i = blockIdx.x * 1024 + tid;
    if (i == 0) g_rowptr[0] = 0;
    if (i < NNODES) {
        int incl = g_rowptr[i + 1] + carry;
        g_rowptr[i + 1] = incl;
        g_off[i] = incl - (g_cnt[i] + 1);
    }
}

// 4 edges per thread + self-loop tail range (NNODES % 4 == 0)
__global__ void scatter_kernel(const int* __restrict__ ei) {
    int idx = blockIdx.x * blockDim.x + threadIdx.x;
    const int EQ = NEDGES / 4;
    if (idx < EQ) {
        int4 s4 = ((const int4*)ei)[idx];
        int4 d4 = ((const int4*)(ei + NEDGES))[idx];
        int p;
        p = atomicAdd(&g_off[d4.x], 1); g_csrc[p] = s4.x;
        p = atomicAdd(&g_off[d4.y], 1); g_csrc[p] = s4.y;
        p = atomicAdd(&g_off[d4.z], 1); g_csrc[p] = s4.z;
        p = atomicAdd(&g_off[d4.w], 1); g_csrc[p] = s4.w;
    } else if (idx < EQ + NNODES / 4) {
        int n0 = (idx - EQ) * 4;
#pragma unroll
        for (int j = 0; j < 4; j++) {
            int n = n0 + j;
            int p = atomicAdd(&g_off[n], 1);
            g_csrc[p] = n;
        }
    }
}

// ---------------- tensor-core helpers ----------------
__device__ __forceinline__ uint32_t smem_u32(const void* p) {
    uint32_t a;
    asm("{ .reg .u64 t; cvta.to.shared.u64 t, %1; cvt.u32.u64 %0, t; }"
        : "=r"(a) : "l"(p));
    return a;
}

__device__ __forceinline__ void ldsm_x4(uint32_t& a0, uint32_t& a1, uint32_t& a2,
                                        uint32_t& a3, uint32_t addr) {
    asm volatile("ldmatrix.sync.aligned.m8n8.x4.shared.b16 {%0,%1,%2,%3}, [%4];"
                 : "=r"(a0), "=r"(a1), "=r"(a2), "=r"(a3) : "r"(addr));
}

__device__ __forceinline__ void ldsm_x2(uint32_t& b0, uint32_t& b1, uint32_t addr) {
    asm volatile("ldmatrix.sync.aligned.m8n8.x2.shared.b16 {%0,%1}, [%2];"
                 : "=r"(b0), "=r"(b1) : "r"(addr));
}

__device__ __forceinline__ void mma16816(float c[4], uint32_t a0, uint32_t a1,
                                         uint32_t a2, uint32_t a3,
                                         uint32_t b0, uint32_t b1) {
    asm volatile(
        "mma.sync.aligned.m16n8k16.row.col.f32.f16.f16.f32 "
        "{%0,%1,%2,%3}, {%4,%5,%6,%7}, {%8,%9}, {%0,%1,%2,%3};"
        : "+f"(c[0]), "+f"(c[1]), "+f"(c[2]), "+f"(c[3])
        : "r"(a0), "r"(a1), "r"(a2), "r"(a3), "r"(b0), "r"(b1));
}

// ---------------- GEMM (HMMA) + fused BN-on-load + alpha epilogue ----------------
__global__ __launch_bounds__(256) void gemm_kernel(
    const float* __restrict__ Xf, const __half* __restrict__ Xh,
    const __half* __restrict__ Wh,
    const float* __restrict__ asrc, const float* __restrict__ adst,
    const float* __restrict__ gamma, const float* __restrict__ beta,
    const float* __restrict__ bsum, const float* __restrict__ bsq,
    int use_bn, int M) {
    extern __shared__ __half smem[];
    __half* Xs = smem;                       // [128][LDX]
    __half* Ws = smem + 128 * LDX;           // [128][LDX]
    float* sc  = (float*)(smem + 2 * 128 * LDX);
    float* sh  = sc + FEAT;
    float* sAs = sh + FEAT;
    float* sAd = sAs + FEAT;

    int tid = threadIdx.x;
    int bm = blockIdx.x * 128;

    if (tid < FEAT) {
        sAs[tid] = asrc[tid];
        sAd[tid] = adst[tid];
        if (use_bn) {
            const float invN = 1.f / (float)NNODES;
            float mu = bsum[tid] * invN;
            float var = bsq[tid] * invN - mu * mu;
            float s = gamma[tid] * rsqrtf(var + BN_EPS);
            sc[tid] = s;
            sh[tid] = beta[tid] - mu * s;
        } else { sc[tid] = 1.f; sh[tid] = 0.f; }
    }
    __syncthreads();

    for (int idx = tid; idx < 2048; idx += 256) {
        int r = idx >> 4, c = (idx & 15) << 3;
        *(uint4*)&Ws[r * LDX + c] = *(const uint4*)&Wh[r * FEAT + c];
    }
    if (Xh) {
        for (int idx = tid; idx < 2048; idx += 256) {
            int r = idx >> 4, c = (idx & 15) << 3;
            int gr = bm + r;
            uint4 u = make_uint4(0u, 0u, 0u, 0u);
            if (gr < M) u = *(const uint4*)&Xh[(size_t)gr * FEAT + c];
            __half2* hp = (__half2*)&u;
            uint4 outv;
            __half2* op = (__half2*)&outv;
#pragma unroll
            for (int j = 0; j < 4; j++) {
                float2 f = __half22float2(hp[j]);
                int cc = c + j * 2;
                float y0 = f.x * sc[cc] + sh[cc];
                float y1 = f.y * sc[cc + 1] + sh[cc + 1];
                y0 = fmaxf(y0, 0.f); y1 = fmaxf(y1, 0.f);
                op[j] = __floats2half2_rn(y0, y1);
            }
            *(uint4*)&Xs[r * LDX + c] = outv;
        }
    } else {
        for (int idx = tid; idx < 4096; idx += 256) {
            int r = idx >> 5, c = (idx & 31) << 2;
            int gr = bm + r;
            float4 xv = make_float4(0.f, 0.f, 0.f, 0.f);
            if (gr < M) xv = *(const float4*)&Xf[(size_t)gr * FEAT + c];
            __half2 h0 = __floats2half2_rn(xv.x, xv.y);
            __half2 h1 = __floats2half2_rn(xv.z, xv.w);
            uint2 u; u.x = *(uint32_t*)&h0; u.y = *(uint32_t*)&h1;
            *(uint2*)&Xs[r * LDX + c] = u;
        }
    }
    __syncthreads();

    int warp = tid >> 5, lane = tid & 31;
    int m0 = warp * 16;

    float c_[16][4];
#pragma unroll
    for (int t = 0; t < 16; t++)
#pragma unroll
        for (int j = 0; j < 4; j++) c_[t][j] = 0.f;

    uint32_t sbase = smem_u32(smem);
    uint32_t xs_addr = sbase + ((m0 + (lane & 15)) * LDX + (lane >> 4) * 8) * 2;
    uint32_t ws_addr = sbase + (128 * LDX + (lane & 7) * LDX + ((lane >> 3) & 1) * 8) * 2;

#pragma unroll
    for (int k = 0; k < 8; k++) {
        uint32_t a0, a1, a2, a3;
        ldsm_x4(a0, a1, a2, a3, xs_addr + k * 32);
#pragma unroll
        for (int t = 0; t < 16; t++) {
            uint32_t b0, b1;
            ldsm_x2(b0, b1, ws_addr + (t * 8 * LDX) * 2 + k * 32);
            mma16816(c_[t], a0, a1, a2, a3, b0, b1);
        }
    }

    // ---- alpha epilogue
    int r0l = lane >> 2;
    int q = (lane & 3) * 2;
    float ps0 = 0.f, pd0 = 0.f, ps1 = 0.f, pd1 = 0.f;
#pragma unroll
    for (int t = 0; t < 16; t++) {
        int cA = t * 8 + q;
        float a0 = sAs[cA], a1 = sAs[cA + 1];
        float d0 = sAd[cA], d1 = sAd[cA + 1];
        ps0 += c_[t][0] * a0 + c_[t][1] * a1;
        pd0 += c_[t][0] * d0 + c_[t][1] * d1;
        ps1 += c_[t][2] * a0 + c_[t][3] * a1;
        pd1 += c_[t][2] * d0 + c_[t][3] * d1;
    }
#pragma unroll
    for (int o = 1; o < 4; o <<= 1) {
        ps0 += __shfl_xor_sync(0xffffffffu, ps0, o);
        pd0 += __shfl_xor_sync(0xffffffffu, pd0, o);
        ps1 += __shfl_xor_sync(0xffffffffu, ps1, o);
        pd1 += __shfl_xor_sync(0xffffffffu, pd1, o);
    }
    int gr0 = bm + m0 + r0l, gr1 = gr0 + 8;
    if ((lane & 3) == 0) {
        if (gr0 < M) { g_as[gr0] = ps0; g_ad[gr0] = pd0; }
        if (gr1 < M) { g_as[gr1] = ps1; g_ad[gr1] = pd1; }
    }

    // ---- stage C (fp16) into this warp's own Xs rows, then coalesced store
#pragma unroll
    for (int t = 0; t < 16; t++) {
        int colp = t * 8 + q;
        __half2 lo = __floats2half2_rn(c_[t][0], c_[t][1]);
        __half2 hi = __floats2half2_rn(c_[t][2], c_[t][3]);
        *(__half2*)&Xs[(m0 + r0l) * LDX + colp] = lo;
        *(__half2*)&Xs[(m0 + r0l + 8) * LDX + colp] = hi;
    }
    __syncwarp();
    for (int i = lane; i < 256; i += 32) {
        int r = i >> 4, ch = (i & 15) << 3;
        int gr = bm + m0 + r;
        if (gr < M)
            *(uint4*)&g_hh[(size_t)gr * FEAT + ch] = *(uint4*)&Xs[(m0 + r) * LDX + ch];
    }
}

__device__ __forceinline__ float leaky(float x) {
    return x >= 0.f ? x : NEG_SLOPE * x;
}

// ---------------- single-pass edge aggregation: half-warp per edge ----------------
__global__ __launch_bounds__(32 * EWARPS) void edge_kernel(const float* __restrict__ bias,
                                                           float* __restrict__ outf,
                                                           __half* __restrict__ outh,
                                                           float* __restrict__ bnsum,
                                                           float* __restrict__ bnsq,
                                                           int do_bn) {
    __shared__ float psum[EWARPS][128];
    __shared__ float psq[EWARPS][128];
    int tid = threadIdx.x, w = tid >> 5, lane = tid & 31;
    int half = lane >> 4, hl = lane & 15;
    int d = blockIdx.x * EWARPS + w;       // grid = NNODES/EWARPS exactly
    int beg = g_rowptr[d], end = g_rowptr[d + 1];
    float ad = g_ad[d];

    float acc[8];
#pragma unroll
    for (int j = 0; j < 8; j++) acc[j] = 0.f;
    float wsum = 0.f;

    const uint4* h4 = (const uint4*)g_hh;   // 16 uint4 per node row
    int i = beg;
#pragma unroll 4
    for (; i + 2 <= end; i += 2) {
        int s = g_csrc[i + half];
        float wt = __expf(leaky(g_as[s] + ad));
        wsum += wt;
        uint4 raw = h4[(size_t)s * 16 + hl];
        __half2* hp = (__half2*)&raw;
#pragma unroll
        for (int j = 0; j < 4; j++) {
            float2 f = __half22float2(hp[j]);
            acc[2 * j]     += wt * f.x;
            acc[2 * j + 1] += wt * f.y;
        }
    }
    if (i < end && half == 0) {            // odd tail edge
        int s = g_csrc[i];
        float wt = __expf(leaky(g_as[s] + ad));
        wsum += wt;
        uint4 raw = h4[(size_t)s * 16 + hl];
        __half2* hp = (__half2*)&raw;
#pragma unroll
        for (int j = 0; j < 4; j++) {
            float2 f = __half22float2(hp[j]);
            acc[2 * j]     += wt * f.x;
            acc[2 * j + 1] += wt * f.y;
        }
    }
#pragma unroll
    for (int j = 0; j < 8; j++)
        acc[j] += __shfl_down_sync(0xffffffffu, acc[j], 16);
    wsum += __shfl_down_sync(0xffffffffu, wsum, 16);

    if (half == 0) {
        float inv = 1.f / wsum;
        float4 b0 = ((const float4*)bias)[hl * 2];
        float4 b1 = ((const float4*)bias)[hl * 2 + 1];
        float o[8];
        o[0] = acc[0] * inv + b0.x; o[1] = acc[1] * inv + b0.y;
        o[2] = acc[2] * inv + b0.z; o[3] = acc[3] * inv + b0.w;
        o[4] = acc[4] * inv + b1.x; o[5] = acc[5] * inv + b1.y;
        o[6] = acc[6] * inv + b1.z; o[7] = acc[7] * inv + b1.w;
        if (outf) {
            ((float4*)outf)[(size_t)d * 32 + hl * 2]     = make_float4(o[0], o[1], o[2], o[3]);
            ((float4*)outf)[(size_t)d * 32 + hl * 2 + 1] = make_float4(o[4], o[5], o[6], o[7]);
        } else {
            __half2 q0 = __floats2half2_rn(o[0], o[1]);
            __half2 q1 = __floats2half2_rn(o[2], o[3]);
            __half2 q2 = __floats2half2_rn(o[4], o[5]);
            __half2 q3 = __floats2half2_rn(o[6], o[7]);
            uint4 u;
            u.x = *(uint32_t*)&q0; u.y = *(uint32_t*)&q1;
            u.z = *(uint32_t*)&q2; u.w = *(uint32_t*)&q3;
            ((uint4*)outh)[(size_t)d * 16 + hl] = u;
        }
        if (do_bn) {
            *(float4*)&psum[w][hl * 8]     = make_float4(o[0], o[1], o[2], o[3]);
            *(float4*)&psum[w][hl * 8 + 4] = make_float4(o[4], o[5], o[6], o[7]);
            *(float4*)&psq[w][hl * 8]      = make_float4(o[0]*o[0], o[1]*o[1], o[2]*o[2], o[3]*o[3]);
            *(float4*)&psq[w][hl * 8 + 4]  = make_float4(o[4]*o[4], o[5]*o[5], o[6]*o[6], o[7]*o[7]);
        }
    }

    if (do_bn) {
        __syncthreads();
        if (tid < FEAT) {
            float s = 0.f, q = 0.f;
#pragma unroll
            for (int ww = 0; ww < EWARPS; ww++) {
                s += psum[ww][tid];
                q += psq[ww][tid];
            }
            atomicAdd(&bnsum[tid], s);
            atomicAdd(&bnsq[tid], q);
        }
    }
}

// ---------------- launch ----------------
extern "C" void kernel_launch(void* const* d_in, const int* in_sizes, int n_in,
                              void* d_out, int out_size) {
    const float* x  = (const float*)d_in[0];
    const int*   ei = (const int*)d_in[1];
    const float* W[3]  = {(const float*)d_in[2], (const float*)d_in[6],  (const float*)d_in[10]};
    const float* As[3] = {(const float*)d_in[3], (const float*)d_in[7],  (const float*)d_in[11]};
    const float* Ad[3] = {(const float*)d_in[4], (const float*)d_in[8],  (const float*)d_in[12]};
    const float* B[3]  = {(const float*)d_in[5], (const float*)d_in[9],  (const float*)d_in[13]};
    const float* gam[2] = {(const float*)d_in[14], (const float*)d_in[16]};
    const float* bet[2] = {(const float*)d_in[15], (const float*)d_in[17]};

    float *bs0, *bq0, *bs1, *bq1;
    __half *wh_ptr, *acch_ptr;
    cudaGetSymbolAddress((void**)&bs0, g_bnsum0);
    cudaGetSymbolAddress((void**)&bq0, g_bnsq0);
    cudaGetSymbolAddress((void**)&bs1, g_bnsum1);
    cudaGetSymbolAddress((void**)&bq1, g_bnsq1);
    cudaGetSymbolAddress((void**)&wh_ptr, g_Wh);
    cudaGetSymbolAddress((void**)&acch_ptr, g_acch);

    const int SMEM_GEMM = (2 * 128 * LDX) * 2 + 4 * FEAT * 4;   // 71680 B
    cudaFuncSetAttribute(gemm_kernel,
                         cudaFuncAttributeMaxDynamicSharedMemorySize, SMEM_GEMM);

    // CSR build (dense)
    convw_kernel<<<(NNODES + 255) / 256, 256>>>(W[0], W[1], W[2]);
    count_kernel<<<(NEDGES / 4 + 255) / 256, 256>>>(ei);
    scan1_kernel<<<SCAN_BLOCKS, 1024>>>();
    scan23_kernel<<<SCAN_BLOCKS, 1024>>>();
    scatter_kernel<<<((NEDGES + NNODES) / 4 + 255) / 256, 256>>>(ei);

    const int gemm_grid = (NNODES + 127) / 128;       // 782
    const int edge_grid = NNODES / EWARPS;            // 6250, exact

    // layer 0 (fp32 X input, no BN)
    gemm_kernel<<<gemm_grid, 256, SMEM_GEMM>>>(x, nullptr, wh_ptr, As[0], Ad[0],
                                               nullptr, nullptr, nullptr, nullptr, 0, NNODES);
    edge_kernel<<<edge_grid, 32 * EWARPS>>>(B[0], nullptr, acch_ptr, bs0, bq0, 1);
    // layer 1 (fp16 X, BN0+relu fused)
    gemm_kernel<<<gemm_grid, 256, SMEM_GEMM>>>(nullptr, acch_ptr, wh_ptr + FEAT * FEAT,
                                               As[1], Ad[1], gam[0], bet[0], bs0, bq0, 1, NNODES);
    edge_kernel<<<edge_grid, 32 * EWARPS>>>(B[1], nullptr, acch_ptr, bs1, bq1, 1);
    // layer 2 (fp16 X, BN1+relu fused, fp32 output)
    gemm_kernel<<<gemm_grid, 256, SMEM_GEMM>>>(nullptr, acch_ptr, wh_ptr + 2 * FEAT * FEAT,
                                               As[2], Ad[2], gam[1], bet[1], bs1, bq1, 1, NNODES);
    edge_kernel<<<edge_grid, 32 * EWARPS>>>(B[2], (float*)d_out, nullptr, nullptr, nullptr, 0);
}